// round 13
// baseline (speedup 1.0000x reference)
#include <cuda_runtime.h>
#include <cstdint>

#define B_TOT   8192
#define NF      32
#define D       64
#define NIX     496
#define BT      128       // batch rows per CTA
#define NTHREADS 64       // 2 warps, each owns M=64 rows, full N=64
#define STRIDE  68        // sP/sK row stride (floats): conflict-free
#define NGRP    136       // sum over r of ceil((31-r)/4)
#define PAIRS_PER_CTA 4

#define SP_F (BT * STRIDE)     // 8704
#define SK_F (64 * STRIDE)     // 4352
#define SMEM_FLOATS (SP_F + SK_F)   // 13056 floats = 52224 B -> 4 CTA/SM

__device__ __forceinline__ float f2tf32(float f) {
    uint32_t r; asm("cvt.rn.tf32.f32 %0, %1;" : "=r"(r) : "f"(f));
    return __uint_as_float(r);
}
__device__ __forceinline__ void mma_tf32(float d[4], const uint32_t a[4], const uint32_t b[2]) {
    asm volatile(
        "mma.sync.aligned.m16n8k8.row.col.f32.tf32.tf32.f32 "
        "{%0,%1,%2,%3}, {%4,%5,%6,%7}, {%8,%9}, {%0,%1,%2,%3};"
        : "+f"(d[0]), "+f"(d[1]), "+f"(d[2]), "+f"(d[3])
        : "r"(a[0]), "r"(a[1]), "r"(a[2]), "r"(a[3]), "r"(b[0]), "r"(b[1]));
}

extern "C" __global__ void __launch_bounds__(NTHREADS, 4)
opn_mma12_kernel(const float* __restrict__ x,
                 const float* __restrict__ kern,
                 float* __restrict__ out)
{
    const int gx   = blockIdx.x;      // pair-group 0..135
    const int bblk = blockIdx.y;
    const int tid  = threadIdx.x;
    const int wid  = tid >> 5;
    const int lane = tid & 31;
    const int b0   = bblk * BT;

    // decode group -> (r, j): groups per r = ceil((31-r)/4) = (34-r)>>2
    int r = 0, g2 = gx;
    while (g2 >= ((34 - r) >> 2)) { g2 -= (34 - r) >> 2; r++; }
    const int cbase = r + 1 + 4 * g2;
    const int nbase = r * 31 - (r * (r - 1)) / 2;

    extern __shared__ float smem[];
    float* sP = smem;
    float* sK = sP + SP_F;

    const int f4 = tid & 15;     // 16B chunk within a 64-float row
    const int rb = tid >> 4;     // 0..3

    // ---------------- P tile (RN tf32) loaded ONCE for the group ----------------
    {
        const float4* xp4 = (const float4*)(x + ((size_t)b0 * NF + r) * D);
        #pragma unroll
        for (int pass = 0; pass < 32; ++pass) {
            int b = rb + pass * 4;
            float4 v = __ldg(xp4 + (size_t)b * (NF * D / 4) + f4);
            float4 t = { f2tf32(v.x), f2tf32(v.y), f2tf32(v.z), f2tf32(v.w) };
            *(float4*)&sP[b * STRIDE + f4 * 4] = t;
        }
    }

    const int g    = lane >> 2;   // 0..7
    const int tig  = lane & 3;    // 0..3
    const int rowW = wid * 64;

    for (int t = 0; t < PAIRS_PER_CTA; ++t) {
        const int c = cbase + t;
        if (c > 31) break;                 // uniform across CTA
        const int n = nbase + (c - r - 1);

        // ---- load K_n (RN tf32) into sK ----
        __syncthreads();                   // previous pair's sK reads done (t=0: P store done)
        #pragma unroll
        for (int pass = 0; pass < 16; ++pass) {
            int o = rb + pass * 4;
            const float4* kp4 = (const float4*)(kern + ((size_t)o * NIX + n) * D);
            float4 v = __ldg(kp4 + f4);
            float4 tt = { f2tf32(v.x), f2tf32(v.y), f2tf32(v.z), f2tf32(v.w) };
            *(float4*)&sK[o * STRIDE + f4 * 4] = tt;
        }
        __syncthreads();

        // ---- MMA main loop: warp owns M=64 rows (mt=0..3), full N=64, K=64 ----
        float acc[4][8][4];
        #pragma unroll
        for (int mt = 0; mt < 4; ++mt)
            #pragma unroll
            for (int q = 0; q < 8; ++q)
                #pragma unroll
                for (int j = 0; j < 4; ++j) acc[mt][q][j] = 0.0f;

        #pragma unroll
        for (int ks = 0; ks < 8; ++ks) {
            const int k0 = ks * 8;
            uint32_t a[4][4];
            #pragma unroll
            for (int mt = 0; mt < 4; ++mt) {
                const int rowA = rowW + mt * 16;
                a[mt][0] = __float_as_uint(sP[(rowA + g)     * STRIDE + k0 + tig]);
                a[mt][1] = __float_as_uint(sP[(rowA + g + 8) * STRIDE + k0 + tig]);
                a[mt][2] = __float_as_uint(sP[(rowA + g)     * STRIDE + k0 + tig + 4]);
                a[mt][3] = __float_as_uint(sP[(rowA + g + 8) * STRIDE + k0 + tig + 4]);
            }
            #pragma unroll
            for (int nt = 0; nt < 8; ++nt) {
                uint32_t b[2];
                b[0] = __float_as_uint(sK[(nt * 8 + g) * STRIDE + k0 + tig]);
                b[1] = __float_as_uint(sK[(nt * 8 + g) * STRIDE + k0 + tig + 4]);
                #pragma unroll
                for (int mt = 0; mt < 4; ++mt)
                    mma_tf32(acc[mt][nt], a[mt], b);
            }
        }

        // ---- epilogue: out[b, n] = sum_o t[b][o] * x[b, c, o] (q from gmem) ----
        #pragma unroll
        for (int mt = 0; mt < 4; ++mt) {
            const int row0 = rowW + mt * 16 + g;
            const float* q0p = x + ((size_t)(b0 + row0)     * NF + c) * D;
            const float* q1p = x + ((size_t)(b0 + row0 + 8) * NF + c) * D;
            float s0 = 0.0f, s1 = 0.0f;
            #pragma unroll
            for (int nt = 0; nt < 8; ++nt) {
                const int col = nt * 8 + tig * 2;
                float2 q0 = __ldg((const float2*)(q0p + col));
                float2 q1 = __ldg((const float2*)(q1p + col));
                s0 = fmaf(acc[mt][nt][0], q0.x, fmaf(acc[mt][nt][1], q0.y, s0));
                s1 = fmaf(acc[mt][nt][2], q1.x, fmaf(acc[mt][nt][3], q1.y, s1));
            }
            s0 += __shfl_xor_sync(0xFFFFFFFFu, s0, 1, 4);
            s0 += __shfl_xor_sync(0xFFFFFFFFu, s0, 2, 4);
            s1 += __shfl_xor_sync(0xFFFFFFFFu, s1, 1, 4);
            s1 += __shfl_xor_sync(0xFFFFFFFFu, s1, 2, 4);
            if (tig == 0) {
                out[(size_t)(b0 + row0)     * NIX + n] = s0;
                out[(size_t)(b0 + row0 + 8) * NIX + n] = s1;
            }
        }
    }
}

extern "C" void kernel_launch(void* const* d_in, const int* in_sizes, int n_in,
                              void* d_out, int out_size)
{
    (void)in_sizes; (void)n_in; (void)out_size;
    const float* x    = (const float*)d_in[0];   // (8192, 32, 64) f32
    const float* kern = (const float*)d_in[1];   // (64, 496, 64) f32
    float* out        = (float*)d_out;           // (8192, 496) f32

    const int smem_bytes = SMEM_FLOATS * (int)sizeof(float);   // 52224
    cudaFuncSetAttribute(opn_mma12_kernel, cudaFuncAttributeMaxDynamicSharedMemorySize, smem_bytes);

    dim3 grid(NGRP, B_TOT / BT);   // (136, 64)
    opn_mma12_kernel<<<grid, NTHREADS, smem_bytes>>>(x, kern, out);
}

// round 14
// speedup vs baseline: 1.1551x; 1.1551x over previous
#include <cuda_runtime.h>
#include <cstdint>

#define B_TOT   8192
#define NF      32
#define D       64
#define NIX     496
#define BT      256       // batch rows per CTA
#define NTHREADS 128      // 4 warps, each owns M=64 rows, full N=64
#define STRIDE  68        // sP/sK row stride (floats): conflict-free
#define QSTRIDE 72        // per-warp q buffer row stride
#define NGRP    136       // sum over r of ceil((31-r)/4)
#define PAIRS_PER_CTA 4

#define SP_F (BT * STRIDE)      // 17408
#define SK_F (64 * STRIDE)      // 4352
#define QB_F (16 * QSTRIDE)     // 1152 per warp
#define SMEM_FLOATS (SP_F + SK_F + 4 * QB_F)   // 26368 floats = 105472 B -> 2 CTA/SM

__device__ __forceinline__ float f2tf32(float f) {
    uint32_t r; asm("cvt.rn.tf32.f32 %0, %1;" : "=r"(r) : "f"(f));
    return __uint_as_float(r);
}
__device__ __forceinline__ void mma_tf32(float d[4], const uint32_t a[4], const uint32_t b[2]) {
    asm volatile(
        "mma.sync.aligned.m16n8k8.row.col.f32.tf32.tf32.f32 "
        "{%0,%1,%2,%3}, {%4,%5,%6,%7}, {%8,%9}, {%0,%1,%2,%3};"
        : "+f"(d[0]), "+f"(d[1]), "+f"(d[2]), "+f"(d[3])
        : "r"(a[0]), "r"(a[1]), "r"(a[2]), "r"(a[3]), "r"(b[0]), "r"(b[1]));
}

extern "C" __global__ void __launch_bounds__(NTHREADS, 2)
opn_mma13_kernel(const float* __restrict__ x,
                 const float* __restrict__ kern,
                 float* __restrict__ out)
{
    const int gx   = blockIdx.x;      // pair-group 0..135
    const int bblk = blockIdx.y;
    const int tid  = threadIdx.x;
    const int wid  = tid >> 5;
    const int lane = tid & 31;
    const int b0   = bblk * BT;

    // decode group -> (r, j): groups per r = ceil((31-r)/4) = (34-r)>>2
    int r = 0, g2 = gx;
    while (g2 >= ((34 - r) >> 2)) { g2 -= (34 - r) >> 2; r++; }
    const int cbase = r + 1 + 4 * g2;
    const int nbase = r * 31 - (r * (r - 1)) / 2;

    extern __shared__ float smem[];
    float* sP = smem;
    float* sK = sP + SP_F;
    float* qb = sK + SK_F + wid * QB_F;   // per-warp q transpose buffer [16][72]

    const int f4 = tid & 15;     // 16B chunk within a 64-float row
    const int rb = tid >> 4;     // 0..7

    // ---------------- P tile (RN tf32) loaded ONCE for the group ----------------
    {
        const float4* xp4 = (const float4*)(x + ((size_t)b0 * NF + r) * D);
        #pragma unroll
        for (int pass = 0; pass < 32; ++pass) {
            int b = rb + pass * 8;
            float4 v = __ldg(xp4 + (size_t)b * (NF * D / 4) + f4);
            float4 t = { f2tf32(v.x), f2tf32(v.y), f2tf32(v.z), f2tf32(v.w) };
            *(float4*)&sP[b * STRIDE + f4 * 4] = t;
        }
    }

    const int g    = lane >> 2;   // 0..7
    const int tig  = lane & 3;    // 0..3
    const int rowW = wid * 64;

    // q-loader mapping: lanes 0-15 -> even-local row, lanes 16-31 -> odd-local row
    const int qhalf = lane >> 4;        // 0 or 1
    const int qcol4 = (lane & 15) * 4;  // 0,4,...,60

    for (int t = 0; t < PAIRS_PER_CTA; ++t) {
        const int c = cbase + t;
        if (c > 31) break;                 // uniform across CTA
        const int n = nbase + (c - r - 1);

        // ---- load K_n (RN tf32) into sK ----
        __syncthreads();                   // previous pair's sK reads done (t=0: P store done)
        #pragma unroll
        for (int pass = 0; pass < 8; ++pass) {
            int o = rb + pass * 8;
            const float4* kp4 = (const float4*)(kern + ((size_t)o * NIX + n) * D);
            float4 v = __ldg(kp4 + f4);
            float4 tt = { f2tf32(v.x), f2tf32(v.y), f2tf32(v.z), f2tf32(v.w) };
            *(float4*)&sK[o * STRIDE + f4 * 4] = tt;
        }
        __syncthreads();

        // ---- MMA main loop: warp owns M=64 rows (mt=0..3), full N=64, K=64 ----
        float acc[4][8][4];
        #pragma unroll
        for (int mt = 0; mt < 4; ++mt)
            #pragma unroll
            for (int q = 0; q < 8; ++q)
                #pragma unroll
                for (int j = 0; j < 4; ++j) acc[mt][q][j] = 0.0f;

        #pragma unroll
        for (int ks = 0; ks < 8; ++ks) {
            const int k0 = ks * 8;
            uint32_t a[4][4];
            #pragma unroll
            for (int mt = 0; mt < 4; ++mt) {
                const int rowA = rowW + mt * 16;
                a[mt][0] = __float_as_uint(sP[(rowA + g)     * STRIDE + k0 + tig]);
                a[mt][1] = __float_as_uint(sP[(rowA + g + 8) * STRIDE + k0 + tig]);
                a[mt][2] = __float_as_uint(sP[(rowA + g)     * STRIDE + k0 + tig + 4]);
                a[mt][3] = __float_as_uint(sP[(rowA + g + 8) * STRIDE + k0 + tig + 4]);
            }
            #pragma unroll
            for (int nt = 0; nt < 8; ++nt) {
                uint32_t b[2];
                b[0] = __float_as_uint(sK[(nt * 8 + g) * STRIDE + k0 + tig]);
                b[1] = __float_as_uint(sK[(nt * 8 + g) * STRIDE + k0 + tig + 4]);
                #pragma unroll
                for (int mt = 0; mt < 4; ++mt)
                    mma_tf32(acc[mt][nt], a[mt], b);
            }
        }

        // ---- epilogue: per-warp smem-transposed Q ----
        // For each mt: stage this warp's 16 q rows coalesced into qb, then do the
        // fragment-layout dot from smem. Only warp-local sync needed.
        #pragma unroll
        for (int mt = 0; mt < 4; ++mt) {
            __syncwarp();                  // prior mt's qb reads complete
            #pragma unroll
            for (int i = 0; i < 8; ++i) {
                const int lrow = 2 * i + qhalf;                 // 0..15
                const int grow = rowW + mt * 16 + lrow;         // global local-CTA row
                float4 v = __ldg((const float4*)(
                    x + ((size_t)(b0 + grow) * NF + c) * D + qcol4));
                *(float4*)&qb[lrow * QSTRIDE + qcol4] = v;
            }
            __syncwarp();

            float s0 = 0.0f, s1 = 0.0f;
            #pragma unroll
            for (int nt = 0; nt < 8; ++nt) {
                const int col = nt * 8 + tig * 2;
                float2 q0 = *(const float2*)&qb[g       * QSTRIDE + col];
                float2 q1 = *(const float2*)&qb[(g + 8) * QSTRIDE + col];
                s0 = fmaf(acc[mt][nt][0], q0.x, fmaf(acc[mt][nt][1], q0.y, s0));
                s1 = fmaf(acc[mt][nt][2], q1.x, fmaf(acc[mt][nt][3], q1.y, s1));
            }
            s0 += __shfl_xor_sync(0xFFFFFFFFu, s0, 1, 4);
            s0 += __shfl_xor_sync(0xFFFFFFFFu, s0, 2, 4);
            s1 += __shfl_xor_sync(0xFFFFFFFFu, s1, 1, 4);
            s1 += __shfl_xor_sync(0xFFFFFFFFu, s1, 2, 4);
            if (tig == 0) {
                const int row0 = rowW + mt * 16 + g;
                out[(size_t)(b0 + row0)     * NIX + n] = s0;
                out[(size_t)(b0 + row0 + 8) * NIX + n] = s1;
            }
        }
    }
}

extern "C" void kernel_launch(void* const* d_in, const int* in_sizes, int n_in,
                              void* d_out, int out_size)
{
    (void)in_sizes; (void)n_in; (void)out_size;
    const float* x    = (const float*)d_in[0];   // (8192, 32, 64) f32
    const float* kern = (const float*)d_in[1];   // (64, 496, 64) f32
    float* out        = (float*)d_out;           // (8192, 496) f32

    const int smem_bytes = SMEM_FLOATS * (int)sizeof(float);   // 105472
    cudaFuncSetAttribute(opn_mma13_kernel, cudaFuncAttributeMaxDynamicSharedMemorySize, smem_bytes);

    dim3 grid(NGRP, B_TOT / BT);   // (136, 32)
    opn_mma13_kernel<<<grid, NTHREADS, smem_bytes>>>(x, kern, out);
}

// round 16
// speedup vs baseline: 1.2854x; 1.1128x over previous
#include <cuda_runtime.h>
#include <cstdint>

#define B_TOT   8192
#define NF      32
#define D       64
#define NIX     496
#define BT      256       // batch rows per CTA
#define NTHREADS 128      // 4 warps, each owns M=64 rows, full N=64
#define STRIDE  68        // sP/sK row stride (floats): conflict-free
#define NGRP    136       // sum over r of ceil((31-r)/4)
#define PAIRS_PER_CTA 4

#define SP_F (BT * STRIDE)     // 17408
#define SK_F (64 * STRIDE)     // 4352
#define SMEM_FLOATS (SP_F + SK_F)   // 21760 floats = 87040 B -> 2 CTA/SM

__device__ __forceinline__ float f2tf32(float f) {
    uint32_t r; asm("cvt.rn.tf32.f32 %0, %1;" : "=r"(r) : "f"(f));
    return __uint_as_float(r);
}
__device__ __forceinline__ void mma_tf32(float d[4], const uint32_t a[4], const uint32_t b[2]) {
    asm volatile(
        "mma.sync.aligned.m16n8k8.row.col.f32.tf32.tf32.f32 "
        "{%0,%1,%2,%3}, {%4,%5,%6,%7}, {%8,%9}, {%0,%1,%2,%3};"
        : "+f"(d[0]), "+f"(d[1]), "+f"(d[2]), "+f"(d[3])
        : "r"(a[0]), "r"(a[1]), "r"(a[2]), "r"(a[3]), "r"(b[0]), "r"(b[1]));
}

extern "C" __global__ void __launch_bounds__(NTHREADS, 2)
opn_mma14_kernel(const float* __restrict__ x,
                 const float* __restrict__ kern,
                 float* __restrict__ out)
{
    const int gx   = blockIdx.x;      // pair-group 0..135
    const int bblk = blockIdx.y;
    const int tid  = threadIdx.x;
    const int wid  = tid >> 5;
    const int lane = tid & 31;
    const int b0   = bblk * BT;

    // decode group -> (r, j): groups per r = ceil((31-r)/4) = (34-r)>>2
    int r = 0, g2 = gx;
    while (g2 >= ((34 - r) >> 2)) { g2 -= (34 - r) >> 2; r++; }
    const int cbase = r + 1 + 4 * g2;
    const int nbase = r * 31 - (r * (r - 1)) / 2;

    extern __shared__ float smem[];
    float* sP = smem;
    float* sK = sP + SP_F;

    const int f4 = tid & 15;     // 16B chunk within a 64-float row
    const int rb = tid >> 4;     // 0..7

    // ---------------- P tile (RN tf32) loaded ONCE for the group ----------------
    {
        const float4* xp4 = (const float4*)(x + ((size_t)b0 * NF + r) * D);
        #pragma unroll
        for (int pass = 0; pass < 32; ++pass) {
            int b = rb + pass * 8;
            float4 v = __ldg(xp4 + (size_t)b * (NF * D / 4) + f4);
            float4 t = { f2tf32(v.x), f2tf32(v.y), f2tf32(v.z), f2tf32(v.w) };
            *(float4*)&sP[b * STRIDE + f4 * 4] = t;
        }
    }
    __syncthreads();

    const int g    = lane >> 2;   // 0..7
    const int tig  = lane & 3;    // 0..3
    const int rowW = wid * 64;

    // ---- A fragments: loaded ONCE per CTA, resident in registers across pairs ----
    uint32_t a_all[8][4][4];      // [ks][mt][frag] = 128 regs
    #pragma unroll
    for (int ks = 0; ks < 8; ++ks) {
        const int k0 = ks * 8;
        #pragma unroll
        for (int mt = 0; mt < 4; ++mt) {
            const int rowA = rowW + mt * 16;
            a_all[ks][mt][0] = __float_as_uint(sP[(rowA + g)     * STRIDE + k0 + tig]);
            a_all[ks][mt][1] = __float_as_uint(sP[(rowA + g + 8) * STRIDE + k0 + tig]);
            a_all[ks][mt][2] = __float_as_uint(sP[(rowA + g)     * STRIDE + k0 + tig + 4]);
            a_all[ks][mt][3] = __float_as_uint(sP[(rowA + g + 8) * STRIDE + k0 + tig + 4]);
        }
    }

    for (int t = 0; t < PAIRS_PER_CTA; ++t) {
        const int c = cbase + t;
        if (c > 31) break;                 // uniform across CTA
        const int n = nbase + (c - r - 1);

        // ---- load K_n (RN tf32) into sK ----
        __syncthreads();                   // previous pair's sK reads done
        #pragma unroll
        for (int pass = 0; pass < 8; ++pass) {
            int o = rb + pass * 8;
            const float4* kp4 = (const float4*)(kern + ((size_t)o * NIX + n) * D);
            float4 v = __ldg(kp4 + f4);
            float4 tt = { f2tf32(v.x), f2tf32(v.y), f2tf32(v.z), f2tf32(v.w) };
            *(float4*)&sK[o * STRIDE + f4 * 4] = tt;
        }
        __syncthreads();

        // ---- nt-outer: MMA for one nt-block, then its epilogue slice, interleaved ----
        float s0[4], s1[4];
        #pragma unroll
        for (int mt = 0; mt < 4; ++mt) { s0[mt] = 0.0f; s1[mt] = 0.0f; }

        #pragma unroll
        for (int nt = 0; nt < 8; ++nt) {
            float acc[4][4];
            #pragma unroll
            for (int mt = 0; mt < 4; ++mt)
                #pragma unroll
                for (int j = 0; j < 4; ++j) acc[mt][j] = 0.0f;

            #pragma unroll
            for (int ks = 0; ks < 8; ++ks) {
                const int k0 = ks * 8;
                uint32_t b[2];
                b[0] = __float_as_uint(sK[(nt * 8 + g) * STRIDE + k0 + tig]);
                b[1] = __float_as_uint(sK[(nt * 8 + g) * STRIDE + k0 + tig + 4]);
                #pragma unroll
                for (int mt = 0; mt < 4; ++mt)
                    mma_tf32(acc[mt], a_all[ks][mt], b);
            }

            // epilogue slice for this nt: q columns [nt*8 + tig*2, +1]
            const int col = nt * 8 + tig * 2;
            #pragma unroll
            for (int mt = 0; mt < 4; ++mt) {
                const int row0 = rowW + mt * 16 + g;
                float2 q0 = __ldg((const float2*)(
                    x + ((size_t)(b0 + row0)     * NF + c) * D + col));
                float2 q1 = __ldg((const float2*)(
                    x + ((size_t)(b0 + row0 + 8) * NF + c) * D + col));
                s0[mt] = fmaf(acc[mt][0], q0.x, fmaf(acc[mt][1], q0.y, s0[mt]));
                s1[mt] = fmaf(acc[mt][2], q1.x, fmaf(acc[mt][3], q1.y, s1[mt]));
            }
        }

        // ---- reduce across the 4-lane tig group and store ----
        #pragma unroll
        for (int mt = 0; mt < 4; ++mt) {
            float v0 = s0[mt], v1 = s1[mt];
            v0 += __shfl_xor_sync(0xFFFFFFFFu, v0, 1, 4);
            v0 += __shfl_xor_sync(0xFFFFFFFFu, v0, 2, 4);
            v1 += __shfl_xor_sync(0xFFFFFFFFu, v1, 1, 4);
            v1 += __shfl_xor_sync(0xFFFFFFFFu, v1, 2, 4);
            if (tig == 0) {
                const int row0 = rowW + mt * 16 + g;
                out[(size_t)(b0 + row0)     * NIX + n] = v0;
                out[(size_t)(b0 + row0 + 8) * NIX + n] = v1;
            }
        }
    }
}

extern "C" void kernel_launch(void* const* d_in, const int* in_sizes, int n_in,
                              void* d_out, int out_size)
{
    (void)in_sizes; (void)n_in; (void)out_size;
    const float* x    = (const float*)d_in[0];   // (8192, 32, 64) f32
    const float* kern = (const float*)d_in[1];   // (64, 496, 64) f32
    float* out        = (float*)d_out;           // (8192, 496) f32

    const int smem_bytes = SMEM_FLOATS * (int)sizeof(float);   // 87040
    cudaFuncSetAttribute(opn_mma14_kernel, cudaFuncAttributeMaxDynamicSharedMemorySize, smem_bytes);

    dim3 grid(NGRP, B_TOT / BT);   // (136, 32)
    opn_mma14_kernel<<<grid, NTHREADS, smem_bytes>>>(x, kern, out);
}